// round 5
// baseline (speedup 1.0000x reference)
#include <cuda_runtime.h>
#include <cstdint>

#define NSEQ 512
#define L 64
#define NTOK (NSEQ*L)          // 32768
#define DM 128
#define DI 256
#define DS 16
#define DTR 8

// ---------------- scratch (floats / u32, 4B each) ----------------
#define OFF_XT    ((size_t)0)                        // NTOK*DM   tf32
#define OFF_XC    (OFF_XT  + (size_t)NTOK*DM)        // NTOK*DI   f32
#define OFF_Z     (OFF_XC  + (size_t)NTOK*DI)        // NTOK*DI   f32
#define OFF_BC    (OFF_Z   + (size_t)NTOK*DI)        // NTOK*32   f32
#define OFF_YT    (OFF_BC  + (size_t)NTOK*32)        // NTOK*DI   tf32
#define OFF_O     (OFF_YT  + (size_t)NTOK*DI)        // NTOK*DM   f32
#define OFF_WT    (OFF_O   + (size_t)NTOK*DM)        // 2*106496 tf32 weights
#define WT_SET    ((size_t)(512*128 + 32*256 + 128*256))   // 106496
#define OFF_STATS (OFF_WT + 2*WT_SET)
#define BUF_TOTAL (OFF_STATS + 64)

__device__ float g_buf[BUF_TOTAL];

__device__ __forceinline__ uint32_t f2tf32(float v) {
    uint32_t r;
    asm("cvt.rna.tf32.f32 %0, %1;" : "=r"(r) : "f"(v));
    return r;
}

__device__ __forceinline__ void mma_tf32(float& c0, float& c1, float& c2, float& c3,
                                         uint32_t a0, uint32_t a1, uint32_t a2, uint32_t a3,
                                         uint32_t b0, uint32_t b1) {
    asm volatile(
        "mma.sync.aligned.m16n8k8.row.col.f32.tf32.tf32.f32 "
        "{%0,%1,%2,%3}, {%4,%5,%6,%7}, {%8,%9}, {%0,%1,%2,%3};"
        : "+f"(c0), "+f"(c1), "+f"(c2), "+f"(c3)
        : "r"(a0), "r"(a1), "r"(a2), "r"(a3), "r"(b0), "r"(b1));
}

// ---------------- fp32 -> tf32 converter (weights) ----------------
__global__ void k_cvt(const float* __restrict__ s, uint32_t* __restrict__ d, int n) {
    int i = blockIdx.x * blockDim.x + threadIdx.x;
    if (i < n) d[i] = f2tf32(s[i]);
}

// ============ tf32 GEMM: C[M,N] = A[M,K] @ W[N,K]^T ============
// BM=128, BN=64, BK=32; 256 threads, 8 warps (4x2), warp tile 32x32.
// ACVT: A is fp32, convert on load (else A already tf32).
// EPI : 0 = plain store to C ; 1 = causal conv + SiLU (Win GEMM, N=512):
//       bn tiles 0..3 -> xc columns -> conv -> XCout ; tiles 4..7 -> Zout.
#define BM 128
#define BN 64
#define BK 32
#define BKP 36

template <int ACVT, int EPI>
__global__ void __launch_bounds__(256) k_gemm_tc(const void* __restrict__ Av,
                                                 const uint32_t* __restrict__ W,
                                                 float* __restrict__ C,
                                                 int N, int K,
                                                 float* __restrict__ XCout,
                                                 float* __restrict__ Zout,
                                                 const float* __restrict__ convw,
                                                 const float* __restrict__ convb) {
    __shared__ union SM {
        struct { uint32_t As[BM][BKP]; uint32_t Ws[BN][BKP]; } g;
        float tile[BM][65];
    } sm;

    int tid = threadIdx.x;
    int warp = tid >> 5, lane = tid & 31;
    int wm = (warp >> 1) * 32;
    int wn = (warp & 1) * 32;
    int bm = blockIdx.y * BM;          // y = M (x fastest over bn => A-tile L2 reuse)
    int bn = blockIdx.x * BN;
    int g = lane >> 2, tg = lane & 3;

    float acc[2][4][4];
#pragma unroll
    for (int mi = 0; mi < 2; mi++)
#pragma unroll
        for (int ni = 0; ni < 4; ni++)
#pragma unroll
            for (int j = 0; j < 4; j++) acc[mi][ni][j] = 0.f;

    const float*    Af = (const float*)Av;
    const uint32_t* At = (const uint32_t*)Av;

    for (int k0 = 0; k0 < K; k0 += BK) {
#pragma unroll
        for (int i = tid; i < BM * 8; i += 256) {
            int row = i >> 3, q = i & 7;
            uint4 u;
            if (ACVT) {
                float4 v = *(const float4*)(Af + (size_t)(bm + row) * K + k0 + q * 4);
                u = make_uint4(f2tf32(v.x), f2tf32(v.y), f2tf32(v.z), f2tf32(v.w));
            } else {
                u = *(const uint4*)(At + (size_t)(bm + row) * K + k0 + q * 4);
            }
            *(uint4*)&sm.g.As[row][q * 4] = u;
        }
#pragma unroll
        for (int i = tid; i < BN * 8; i += 256) {
            int row = i >> 3, q = i & 7;
            uint4 u = make_uint4(0u, 0u, 0u, 0u);
            if (bn + row < N)
                u = *(const uint4*)(W + (size_t)(bn + row) * K + k0 + q * 4);
            *(uint4*)&sm.g.Ws[row][q * 4] = u;
        }
        __syncthreads();

#pragma unroll
        for (int kk = 0; kk < BK; kk += 8) {
            uint32_t a[2][4], b[4][2];
#pragma unroll
            for (int mi = 0; mi < 2; mi++) {
                int r0 = wm + mi * 16;
                a[mi][0] = sm.g.As[r0 + g][kk + tg];
                a[mi][1] = sm.g.As[r0 + 8 + g][kk + tg];
                a[mi][2] = sm.g.As[r0 + g][kk + 4 + tg];
                a[mi][3] = sm.g.As[r0 + 8 + g][kk + 4 + tg];
            }
#pragma unroll
            for (int ni = 0; ni < 4; ni++) {
                int r0 = wn + ni * 8 + g;
                b[ni][0] = sm.g.Ws[r0][kk + tg];
                b[ni][1] = sm.g.Ws[r0][kk + 4 + tg];
            }
#pragma unroll
            for (int mi = 0; mi < 2; mi++)
#pragma unroll
                for (int ni = 0; ni < 4; ni++)
                    mma_tf32(acc[mi][ni][0], acc[mi][ni][1], acc[mi][ni][2], acc[mi][ni][3],
                             a[mi][0], a[mi][1], a[mi][2], a[mi][3],
                             b[ni][0], b[ni][1]);
        }
        __syncthreads();
    }

    if (EPI == 0) {
        // plain epilogue
#pragma unroll
        for (int mi = 0; mi < 2; mi++) {
            int row0 = bm + wm + mi * 16 + g;
#pragma unroll
            for (int ni = 0; ni < 4; ni++) {
                int col = bn + wn + ni * 8 + tg * 2;
                if (col < N) {
                    *(float2*)(C + (size_t)row0 * N + col) =
                        make_float2(acc[mi][ni][0], acc[mi][ni][1]);
                    *(float2*)(C + (size_t)(row0 + 8) * N + col) =
                        make_float2(acc[mi][ni][2], acc[mi][ni][3]);
                }
            }
        }
    } else {
        // stage accumulators into smem tile (128 rows = 2 full sequences, 64 cols)
#pragma unroll
        for (int mi = 0; mi < 2; mi++) {
            int r0 = wm + mi * 16 + g;
#pragma unroll
            for (int ni = 0; ni < 4; ni++) {
                int col = wn + ni * 8 + tg * 2;
                sm.tile[r0][col]     = acc[mi][ni][0];
                sm.tile[r0][col + 1] = acc[mi][ni][1];
                sm.tile[r0 + 8][col]     = acc[mi][ni][2];
                sm.tile[r0 + 8][col + 1] = acc[mi][ni][3];
            }
        }
        __syncthreads();

        bool is_xc = (blockIdx.x < 4);
        int col = tid & 63;
        int d = (is_xc ? blockIdx.x : blockIdx.x - 4) * 64 + col;
        float w0 = 0.f, w1 = 0.f, w2 = 0.f, w3 = 0.f, cb = 0.f;
        if (is_xc) {
            w0 = convw[d * 4 + 0]; w1 = convw[d * 4 + 1];
            w2 = convw[d * 4 + 2]; w3 = convw[d * 4 + 3];
            cb = convb[d];
        }
#pragma unroll
        for (int rg = tid >> 6; rg < BM; rg += 4) {
            float xt = sm.tile[rg][col];
            size_t m = (size_t)(bm + rg) * DI + d;
            if (is_xc) {
                int t = rg & 63;
                float x1 = (t >= 1) ? sm.tile[rg - 1][col] : 0.f;
                float x2 = (t >= 2) ? sm.tile[rg - 2][col] : 0.f;
                float x3 = (t >= 3) ? sm.tile[rg - 3][col] : 0.f;
                float a = fmaf(w0, x3, fmaf(w1, x2, fmaf(w2, x1, fmaf(w3, xt, cb))));
                float sg = 1.f / (1.f + __expf(-a));
                XCout[m] = a * sg;
            } else {
                Zout[m] = xt;
            }
        }
    }
}

// ---------------- input transpose: x[B,C,H,W] -> XT[(b,h,w)][c] (tf32) ----------------
__global__ void k_transpose_in(const float* __restrict__ x, uint32_t* __restrict__ XT) {
    __shared__ float tile[32][33];
    int bh = blockIdx.z;
    int b = bh >> 6, h = bh & 63;
    int w0 = blockIdx.x * 32;
    int c0 = blockIdx.y * 32;
    int tx = threadIdx.x, ty = threadIdx.y;
#pragma unroll
    for (int i = ty; i < 32; i += 8)
        tile[i][tx] = x[((size_t)(b * DM + c0 + i) * 64 + h) * 64 + w0 + tx];
    __syncthreads();
#pragma unroll
    for (int i = ty; i < 32; i += 8)
        XT[((size_t)bh * 64 + w0 + i) * DM + c0 + tx] = f2tf32(tile[tx][i]);
}

// ---------------- fused scan: fp32 dt projection + softplus + recurrence + gate ----------------
// grid = NSEQ, 256 threads. Emits Y in tf32 for the Wout GEMM.
__global__ void __launch_bounds__(256) k_scan(const float* __restrict__ XC,
                                              const float* __restrict__ BC,
                                              const float* __restrict__ Z,
                                              const float* __restrict__ Wx,   // orig [40][256], rows 0..7 = dt proj
                                              const float* __restrict__ Wdt,  // [256][8]
                                              const float* __restrict__ bdt,
                                              const float* __restrict__ Alog,
                                              const float* __restrict__ Dvec,
                                              uint32_t* __restrict__ YT) {
    extern __shared__ float smem[];
    float* sx  = smem;               // [64][260]
    float* swx = sx + 64 * 260;      // [8][260]
    float* sbc = swx + 8 * 260;      // [64][32]
    float* sdt = sbc + 64 * 32;      // [64][8]

    int seq = blockIdx.x;
    int tid = threadIdx.x;
    const float* xcg = XC + (size_t)seq * L * DI;

    for (int i = tid; i < L * (DI / 4); i += 256) {
        int t = i >> 6, q = i & 63;
        float4 v = ((const float4*)xcg)[i];
        *(float4*)&sx[t * 260 + q * 4] = v;
    }
    for (int i = tid; i < 8 * (DI / 4); i += 256) {
        int r = i >> 6, q = i & 63;
        float4 v = ((const float4*)Wx)[i];
        *(float4*)&swx[r * 260 + q * 4] = v;
    }
    for (int i = tid; i < L * 8; i += 256) {
        int t = i >> 3, q = i & 7;
        float4 v = ((const float4*)(BC + (size_t)seq * L * 32))[i];
        *(float4*)&sbc[t * 32 + q * 4] = v;
    }
    __syncthreads();

    // stage 1: dtraw[t][r] = XC[t,:] . Wx[r,:]   (fp32)
    {
        int t = tid >> 2, rr = tid & 3;
        float a0 = 0.f, a1 = 0.f;
        for (int k = 0; k < DI; k += 4) {
            float4 xv = *(float4*)&sx[t * 260 + k];
            float4 wa = *(float4*)&swx[rr * 260 + k];
            float4 wb = *(float4*)&swx[(rr + 4) * 260 + k];
            a0 = fmaf(xv.x, wa.x, fmaf(xv.y, wa.y, fmaf(xv.z, wa.z, fmaf(xv.w, wa.w, a0))));
            a1 = fmaf(xv.x, wb.x, fmaf(xv.y, wb.y, fmaf(xv.z, wb.z, fmaf(xv.w, wb.w, a1))));
        }
        sdt[t * 8 + rr] = a0;
        sdt[t * 8 + rr + 4] = a1;
    }
    __syncthreads();

    int d = tid;
    float wdt[DTR];
#pragma unroll
    for (int r = 0; r < DTR; r++) wdt[r] = Wdt[d * DTR + r];
    float bd = bdt[d], Dd = Dvec[d];
    float A[DS];
#pragma unroll
    for (int s = 0; s < DS; s++) A[s] = -__expf(Alog[d * DS + s]);
    float h[DS];
#pragma unroll
    for (int s = 0; s < DS; s++) h[s] = 0.f;

    const float* zrow = Z + (size_t)seq * L * DI + d;
    uint32_t* yrow = YT + (size_t)seq * L * DI + d;

    for (int t = 0; t < L; t++) {
        float dtr = bd;
#pragma unroll
        for (int r = 0; r < DTR; r++) dtr = fmaf(sdt[t * 8 + r], wdt[r], dtr);
        float dt = (dtr > 20.f) ? dtr : log1pf(__expf(dtr));
        float xv = sx[t * 260 + d];
        float zv = zrow[(size_t)t * DI];
        float dx = dt * xv;
        float accy = 0.f;
#pragma unroll
        for (int s = 0; s < DS; s++) {
            float e = __expf(dt * A[s]);
            h[s] = fmaf(h[s], e, dx * sbc[t * 32 + s]);
            accy = fmaf(h[s], sbc[t * 32 + 16 + s], accy);
        }
        float y = fmaf(xv, Dd, accy);
        float sg = 1.f / (1.f + __expf(-zv));
        yrow[(size_t)t * DI] = f2tf32(y * (zv * sg));
    }
}

// ---------------- inter-pass row permutation, emits tf32 ----------------
__global__ void k_permute(const float4* __restrict__ src, uint4* __restrict__ dst) {
    int gid = blockIdx.x * blockDim.x + threadIdx.x;   // NTOK*32 float4s
    int r = gid >> 5, c = gid & 31;
    int b = r >> 12, h = (r >> 6) & 63, w = r & 63;
    int r2 = (b << 12) | (w << 6) | h;
    float4 v = src[(size_t)r * 32 + c];
    dst[(size_t)r2 * 32 + c] = make_uint4(f2tf32(v.x), f2tf32(v.y), f2tf32(v.z), f2tf32(v.w));
}

// ---------------- GroupNorm stats ----------------
__global__ void __launch_bounds__(256) k_gn_reduce(const float* __restrict__ O,
                                                   float* __restrict__ stats) {
    int bg = blockIdx.x;
    int b = bg >> 2, g = bg & 3;
    int c0 = g * 32;
    float sum = 0.f, ss = 0.f;
    for (int i = threadIdx.x; i < 32 * 4096; i += 256) {
        int c = c0 + (i & 31);
        int hw = i >> 5;
        float v = O[((size_t)b * 4096 + hw) * DM + c];
        sum += v;
        ss = fmaf(v, v, ss);
    }
    __shared__ float s1[256], s2[256];
    s1[threadIdx.x] = sum; s2[threadIdx.x] = ss;
    __syncthreads();
    for (int st = 128; st > 0; st >>= 1) {
        if (threadIdx.x < st) {
            s1[threadIdx.x] += s1[threadIdx.x + st];
            s2[threadIdx.x] += s2[threadIdx.x + st];
        }
        __syncthreads();
    }
    if (threadIdx.x == 0) {
        float n = 32.f * 4096.f;
        float mu = s1[0] / n;
        float var = s2[0] / n - mu * mu;
        stats[bg * 2] = mu;
        stats[bg * 2 + 1] = rsqrtf(var + 1e-5f);
    }
}

// ---------------- normalize + SiLU + transpose out ----------------
__global__ void k_gn_write(const float* __restrict__ O, const float* __restrict__ stats,
                           const float* __restrict__ gamma, const float* __restrict__ beta,
                           float* __restrict__ out) {
    __shared__ float tile[32][33];
    int bh = blockIdx.z;
    int b = bh >> 6, h = bh & 63;
    int w0 = blockIdx.x * 32;
    int c0 = blockIdx.y * 32;
    int tx = threadIdx.x, ty = threadIdx.y;
#pragma unroll
    for (int i = ty; i < 32; i += 8)
        tile[i][tx] = O[((size_t)(b * 64 + w0 + i) * 64 + h) * DM + c0 + tx];
    __syncthreads();
    int g = c0 >> 5;
    float mu = stats[(b * 4 + g) * 2];
    float istd = stats[(b * 4 + g) * 2 + 1];
#pragma unroll
    for (int i = ty; i < 32; i += 8) {
        int c = c0 + i;
        float v = (tile[tx][i] - mu) * istd * gamma[c] + beta[c];
        float sg = 1.f / (1.f + __expf(-v));
        out[((size_t)(b * DM + c) * 64 + h) * 64 + w0 + tx] = v * sg;
    }
}

// ---------------- host ----------------
extern "C" void kernel_launch(void* const* d_in, const int* in_sizes, int n_in,
                              void* d_out, int out_size) {
    const float* x = (const float*)d_in[0];
    const float* rW[9];
    const float* cW[9];
    for (int i = 0; i < 9; i++) rW[i] = (const float*)d_in[1 + i];
    for (int i = 0; i < 9; i++) cW[i] = (const float*)d_in[10 + i];
    const float* gamma = (const float*)d_in[19];
    const float* beta  = (const float*)d_in[20];
    float* out = (float*)d_out;

    float* buf = nullptr;
    cudaGetSymbolAddress((void**)&buf, g_buf);
    uint32_t* XT = (uint32_t*)(buf + OFF_XT);
    float*    XC = buf + OFF_XC;
    float*    Zb = buf + OFF_Z;
    float*    BC = buf + OFF_BC;
    uint32_t* YT = (uint32_t*)(buf + OFF_YT);
    float*    O  = buf + OFF_O;
    uint32_t* WT = (uint32_t*)(buf + OFF_WT);
    float*    ST = buf + OFF_STATS;

    static bool attr_done = false;
    if (!attr_done) {
        cudaFuncSetAttribute(k_scan, cudaFuncAttributeMaxDynamicSharedMemorySize, 90 * 1024);
        attr_done = true;
    }
    const int scan_smem = (64 * 260 + 8 * 260 + 64 * 32 + 64 * 8) * 4;  // ~85 KB

    // weight tf32 prep: per set: Win[512*128] | Wx rows 8..39 [32*256] | Wout [128*256]
    for (int p = 0; p < 2; p++) {
        const float* const* Wp = (p == 0) ? rW : cW;
        uint32_t* wt = WT + p * WT_SET;
        k_cvt<<<(512 * 128 + 255) / 256, 256>>>(Wp[0], wt, 512 * 128);
        k_cvt<<<(32 * 256 + 255) / 256, 256>>>(Wp[3] + 8 * 256, wt + 512 * 128, 32 * 256);
        k_cvt<<<(128 * 256 + 255) / 256, 256>>>(Wp[8], wt + 512 * 128 + 32 * 256, 128 * 256);
    }

    dim3 tb(32, 8);
    k_transpose_in<<<dim3(2, 4, 512), tb>>>(x, XT);

    for (int p = 0; p < 2; p++) {
        const float* const* Wp = (p == 0) ? rW : cW;
        uint32_t* wt = WT + p * WT_SET;
        uint32_t* WinT  = wt;
        uint32_t* WxT   = wt + 512 * 128;
        uint32_t* WoutT = wt + 512 * 128 + 32 * 256;

        // Win GEMM + fused conv/SiLU epilogue: XT @ Win^T -> XC (cols 0..255), Z (256..511)
        k_gemm_tc<0, 1><<<dim3(8, NTOK / BM), 256>>>(XT, WinT, nullptr, 512, DM,
                                                     XC, Zb, Wp[1], Wp[2]);
        // Wx GEMM (B,C only, rows 8..39): XC @ WxT^T -> BC [NTOK][32]
        k_gemm_tc<1, 0><<<dim3(1, NTOK / BM), 256>>>(XC, WxT, BC, 32, DI,
                                                     nullptr, nullptr, nullptr, nullptr);
        // fused dt-projection + softplus + selective scan + gate -> YT (tf32)
        k_scan<<<NSEQ, 256, scan_smem>>>(XC, BC, Zb, Wp[3], Wp[4], Wp[5], Wp[6], Wp[7], YT);
        // Wout GEMM: YT @ Wout^T -> O
        k_gemm_tc<0, 0><<<dim3(2, NTOK / BM), 256>>>(YT, WoutT, O, DM, DI,
                                                     nullptr, nullptr, nullptr, nullptr);
        if (p == 0)
            k_permute<<<(NTOK * 32) / 256, 256>>>((const float4*)O, (uint4*)XT);
    }

    k_gn_reduce<<<32, 256>>>(O, ST);
    k_gn_write<<<dim3(2, 4, 512), tb>>>(O, ST, gamma, beta, out);
}